// round 11
// baseline (speedup 1.0000x reference)
#include <cuda_runtime.h>
#include <cuda_bf16.h>
#include <cstdint>

#define BATCH 4
#define NC 32
#define CIN 224
#define VOL 32768
#define KT 16512

__device__ float  g_state[BATCH * NC * VOL];
__device__ float  g_feat [BATCH * CIN * VOL];
__device__ double g_sumd [BATCH * CIN];
__device__ double g_sqd  [BATCH * CIN];
__device__ float  g_w    [BATCH * KT];

// offsets (floats) inside per-batch g_w block
#define WC_OFF  0       // [224 k][64 o]: o 0..31 = W_in', 32..63 = W_sh'
#define B64_OFF 14336
#define WM_OFF  14400
#define BM_OFF  15424
#define WO_OFF  15456
#define BO_OFF  16480

#define FMA2(acc, w, x) asm("fma.rn.f32x2 %0, %1, %2, %0;" : "+l"(acc) : "l"(w), "l"(x))
#define BCAST(d, f)     asm("mov.b64 %0, {%1, %1};" : "=l"(d) : "f"(f))
#define UNPK(lo, hi, q) asm("mov.b64 {%0, %1}, %2;" : "=f"(lo), "=f"(hi) : "l"(q))
#define CPA16(dst, src) asm volatile("cp.async.cg.shared.global [%0], [%1], 16;" :: "r"(dst), "l"(src))
#define CPCOMMIT()      asm volatile("cp.async.commit_group;")
#define CPWAIT(n)       asm volatile("cp.async.wait_group %0;" :: "n"(n))

// ---------------- init (z-normalize inline) ----------------

__global__ void k_init(const float* __restrict__ z) {
    int b = blockIdx.y;
    int v = (blockIdx.x << 8) + threadIdx.x;
    float val = 0.f;
    if (blockIdx.x < 2) {
        __shared__ float sh[8];
        __shared__ float snorm;
        int t = threadIdx.x;
        float v0 = z[b * 512 + t], v1 = z[b * 512 + 256 + t];
        float s = v0 * v0 + v1 * v1;
        #pragma unroll
        for (int o = 16; o; o >>= 1) s += __shfl_down_sync(~0u, s, o);
        if ((t & 31) == 0) sh[t >> 5] = s;
        __syncthreads();
        if (t < 8) {
            float x = sh[t];
            #pragma unroll
            for (int o = 4; o; o >>= 1) x += __shfl_down_sync(0xffu, x, o);
            if (t == 0) snorm = fmaxf(sqrtf(x), 1e-12f);
        }
        __syncthreads();
        val = z[b * 512 + v] / snorm;
    }
    #pragma unroll
    for (int c = 0; c < NC; c++) g_state[((b * NC + c) << 15) + v] = val;
}

// ---------------- sobel (best-known R5) ----------------

__global__ void __launch_bounds__(512) k_sobel() {
    __shared__ float sl[2][4][36][32];
    __shared__ float red[16][14];
    const int c = blockIdx.x, b = blockIdx.y;
    const int tid = threadIdx.x;
    const int lane = tid & 31, wid = tid >> 5;
    const int h0 = wid * 2;
    const float* __restrict__ xin = g_state + ((size_t)(b * NC + c) << 15);
    float* __restrict__ featb = g_feat + (size_t)(b * CIN + c) * VOL;

    for (int i = tid; i < 1024; i += 512) {
        int w = i & 31, r = (i >> 5) & 3, arr = (i >> 7) & 3, bu = i >> 9;
        int hp = (r < 2) ? r : r + 32;
        sl[bu][arr][hp][w] = 0.f;
    }

    const float R2 = 0.70710678118654752f;
    const float S1 = 1.f + R2;

    float stat[14];
    #pragma unroll
    for (int i = 0; i < 14; i++) stat[i] = 0.f;
    float W[2][6][5];
    #pragma unroll
    for (int r = 0; r < 2; r++)
        #pragma unroll
        for (int a = 0; a < 6; a++)
            #pragma unroll
            for (int k = 0; k < 5; k++) W[r][a][k] = 0.f;

    float xc[2];
    xc[0] = xin[((h0 + 0) << 5) + lane];
    xc[1] = xin[((h0 + 1) << 5) + lane];

    __syncthreads();

    float sw3[2], dw3[2], sw5[2], dw5[2];

    #pragma unroll 2
    for (int s = 0; s < 34; s++) {
        const int bu = s & 1;
        float xn0 = 0.f, xn1 = 0.f;
        if (s + 1 < 32) {
            xn0 = xin[((s + 1) << 10) + ((h0 + 0) << 5) + lane];
            xn1 = xin[((s + 1) << 10) + ((h0 + 1) << 5) + lane];
        }
        if (s < 32) {
            #pragma unroll
            for (int r = 0; r < 2; r++) {
                float xv = xc[r];
                stat[0] += xv; stat[1] += xv * xv;
                float xm1 = __shfl_up_sync(~0u, xv, 1);   if (lane == 0)  xm1 = 0.f;
                float xm2 = __shfl_up_sync(~0u, xv, 2);   if (lane < 2)   xm2 = 0.f;
                float xp1 = __shfl_down_sync(~0u, xv, 1); if (lane == 31) xp1 = 0.f;
                float xp2 = __shfl_down_sync(~0u, xv, 2); if (lane > 29)  xp2 = 0.f;
                sw3[r] = xm1 + 2.f * xv + xp1;
                dw3[r] = xp1 - xm1;
                sw5[r] = xm2 + xp2 + S1 * (xm1 + xp1) + 2.f * xv;
                dw5[r] = (xp2 - xm2) + R2 * (xp1 - xm1);
                int hp = h0 + r + 2;
                sl[bu][0][hp][lane] = sw3[r];
                sl[bu][1][hp][lane] = dw3[r];
                sl[bu][2][hp][lane] = sw5[r];
                sl[bu][3][hp][lane] = dw5[r];
            }
        }
        xc[0] = xn0; xc[1] = xn1;
        __syncthreads();
        #pragma unroll
        for (int r = 0; r < 2; r++) {
            float a30, a31, a32, a50, a51, a52;
            if (s < 32) {
                int hp = h0 + r + 2;
                float s3m = sl[bu][0][hp - 1][lane], s3p = sl[bu][0][hp + 1][lane];
                float d3m = sl[bu][1][hp - 1][lane], d3p = sl[bu][1][hp + 1][lane];
                float s5m2 = sl[bu][2][hp - 2][lane], s5m1 = sl[bu][2][hp - 1][lane];
                float s5p1 = sl[bu][2][hp + 1][lane], s5p2 = sl[bu][2][hp + 2][lane];
                float d5m2 = sl[bu][3][hp - 2][lane], d5m1 = sl[bu][3][hp - 1][lane];
                float d5p1 = sl[bu][3][hp + 1][lane], d5p2 = sl[bu][3][hp + 2][lane];
                a30 = d3m + 2.f * dw3[r] + d3p;
                a31 = s3p - s3m;
                a32 = s3m + 2.f * sw3[r] + s3p;
                a50 = d5m2 + d5p2 + S1 * (d5m1 + d5p1) + 2.f * dw5[r];
                a51 = (s5p2 - s5m2) + R2 * (s5p1 - s5m1);
                a52 = s5m2 + s5p2 + S1 * (s5m1 + s5p1) + 2.f * sw5[r];
            } else {
                a30 = a31 = a32 = a50 = a51 = a52 = 0.f;
            }
            #pragma unroll
            for (int a = 0; a < 6; a++) {
                W[r][a][0] = W[r][a][1]; W[r][a][1] = W[r][a][2];
                W[r][a][2] = W[r][a][3]; W[r][a][3] = W[r][a][4];
            }
            W[r][0][4] = a32; W[r][1][4] = a31; W[r][2][4] = a30;
            W[r][3][4] = a52; W[r][4][4] = a51; W[r][5][4] = a50;

            if (s >= 2) {
                int dc = s - 2;
                float o1 = W[r][0][3] - W[r][0][1];
                float o2 = W[r][1][1] + 2.f * W[r][1][2] + W[r][1][3];
                float o3 = W[r][2][1] + 2.f * W[r][2][2] + W[r][2][3];
                float o4 = (W[r][3][4] - W[r][3][0]) + R2 * (W[r][3][3] - W[r][3][1]);
                float o5 = W[r][4][0] + W[r][4][4] + S1 * (W[r][4][1] + W[r][4][3]) + 2.f * W[r][4][2];
                float o6 = W[r][5][0] + W[r][5][4] + S1 * (W[r][5][1] + W[r][5][3]) + 2.f * W[r][5][2];
                int v = (dc << 10) + ((h0 + r) << 5) + lane;
                featb[(size_t)32 * VOL + v]  = o1;
                featb[(size_t)64 * VOL + v]  = o2;
                featb[(size_t)96 * VOL + v]  = o3;
                featb[(size_t)128 * VOL + v] = o4;
                featb[(size_t)160 * VOL + v] = o5;
                featb[(size_t)192 * VOL + v] = o6;
                stat[2]  += o1; stat[3]  += o1 * o1;
                stat[4]  += o2; stat[5]  += o2 * o2;
                stat[6]  += o3; stat[7]  += o3 * o3;
                stat[8]  += o4; stat[9]  += o4 * o4;
                stat[10] += o5; stat[11] += o5 * o5;
                stat[12] += o6; stat[13] += o6 * o6;
            }
        }
    }

    #pragma unroll
    for (int i = 0; i < 14; i++) {
        float v = stat[i];
        #pragma unroll
        for (int o = 16; o; o >>= 1) v += __shfl_down_sync(~0u, v, o);
        stat[i] = v;
    }
    if (lane == 0)
        #pragma unroll
        for (int i = 0; i < 14; i++) red[wid][i] = stat[i];
    __syncthreads();
    if (tid < 14) {
        double acc = 0.0;
        #pragma unroll
        for (int k = 0; k < 16; k++) acc += (double)red[k][tid];
        int g = tid >> 1;
        if (tid & 1) g_sqd [b * CIN + g * 32 + c] = acc;
        else         g_sumd[b * CIN + g * 32 + c] = acc;
    }
}

// ---------------- fold norm into weights (theta inlined) ----------------

__global__ void k_fold(const int* __restrict__ y, const float* __restrict__ hw,
                       const float* __restrict__ hb) {
    int b = blockIdx.x, tid = threadIdx.x;
    int lane = tid & 31, wid = tid >> 5;
    __shared__ float smean[CIN], srs[CIN];
    if (tid < CIN) {
        double m = g_sumd[b * CIN + tid] * (1.0 / 32768.0);
        double var = g_sqd[b * CIN + tid] * (1.0 / 32768.0) - m * m;
        smean[tid] = (float)m;
        srs[tid] = (float)rsqrt(var + 1e-5);
    }
    __syncthreads();
    const float* th = hw + (size_t)y[b] * KT;
    float* w = g_w + b * KT;
    #pragma unroll
    for (int j = 0; j < 8; j++) {
        int o = wid * 8 + j;
        int off = (o < 32) ? o * 224 : 9312 + (o - 32) * 224;
        float corr = 0.f;
        #pragma unroll
        for (int q = 0; q < 7; q++) {
            int cc = lane + q * 32;
            float wv = (th[off + cc] + hb[off + cc]) * srs[cc];
            w[WC_OFF + cc * 64 + o] = wv;
            corr += wv * smean[cc];
        }
        #pragma unroll
        for (int d = 16; d; d >>= 1) corr += __shfl_down_sync(~0u, corr, d);
        if (lane == 0) {
            float braw = (o < 32) ? (th[7168 + o] + hb[7168 + o])
                                  : (th[16480 + o - 32] + hb[16480 + o - 32]);
            w[B64_OFF + o] = braw - corr;
        }
    }
    for (int i = tid; i < 1024; i += 256) {
        int r = i >> 5, cc = i & 31;
        w[WM_OFF + cc * 32 + r] = th[7200 + r * 32 + cc] + hb[7200 + r * 32 + cc];
        w[WO_OFF + cc * 32 + r] = th[8256 + r * 32 + cc] + hb[8256 + r * 32 + cc];
    }
    if (tid < 32) {
        w[BM_OFF + tid] = th[8224 + tid] + hb[8224 + tid];
        w[BO_OFF + tid] = th[9280 + tid] + hb[9280 + tid];
    }
}

// ---------------- residual MLP: 64 out x 256 vox tile ----------------
// 256 threads; thread = 16 out x 4 vox (32 f32x2 accs). 16-ch chunks,
// 3-slot cp.async ring. Stage 2 fully per-thread (v = tid, 32 outputs).
// smem floats: XS [3][16][256]=12288 | WS [3][16][64]=3072 (ring, [0,15360))
//   HSO [64][260]=16640 unions ring after stage 1; SWB at 16640 (2176 fl)
#define XS   0
#define WS   12288
#define HSO  0
#define SWB  16640
#define SM_FLOATS 18816

__global__ void __launch_bounds__(256) k_residual(float* __restrict__ out, int last) {
    extern __shared__ float sm[];
    const int tid = threadIdx.x;
    const int wid = tid >> 5, lane = tid & 31;
    const int b = blockIdx.y;
    const int v0 = blockIdx.x << 8;
    const float* gw = g_w + b * KT;
    unsigned swa = (unsigned)__cvta_generic_to_shared(sm);

    // stage-2 weights -> smem
    if (tid < 64)  sm[SWB + tid]       = gw[B64_OFF + tid];
    if (tid < 32)  sm[SWB + 64 + tid]  = gw[BM_OFF + tid];
    if (tid >= 32 && tid < 64) sm[SWB + 96 + (tid - 32)] = gw[BO_OFF + tid - 32];
    for (int i = tid; i < 1024; i += 256) sm[SWB + 128 + i]  = gw[WM_OFF + i];
    for (int i = tid; i < 1024; i += 256) sm[SWB + 1152 + i] = gw[WO_OFF + i];

    // chunk copy: x 16x256 (4 CPA16/thread), w 16x64 (1 CPA16/thread)
    const int xr = tid >> 4, xc4 = (tid & 15) * 16;   // row 0..15, float offset
    auto issue = [&](int ch) {
        int slot = ch % 3;
        int cc = ch * 16 + xr;
        const float* xsrc = (cc < 32)
            ? g_state + ((size_t)(b * NC + cc) << 15) + v0 + xc4
            : g_feat  + ((size_t)(b * CIN + cc) << 15) + v0 + xc4;
        unsigned xdst = swa + (XS + slot * 4096 + xr * 256 + xc4) * 4;
        CPA16(xdst,      xsrc);
        CPA16(xdst + 16, xsrc + 4);
        CPA16(xdst + 32, xsrc + 8);
        CPA16(xdst + 48, xsrc + 12);
        const float* wsrc = gw + WC_OFF + (ch * 16 + xr) * 64 + (tid & 15) * 4;
        CPA16(swa + (WS + slot * 1024 + xr * 64 + (tid & 15) * 4) * 4, wsrc);
    };

    issue(0); CPCOMMIT();
    issue(1); CPCOMMIT();

    const int obase = (wid & 3) * 16;        // 16 outputs
    const int vbase = (wid >> 2) * 128;      // + lane*4 -> 4 voxels

    unsigned long long acc[32];
    #pragma unroll
    for (int i = 0; i < 32; i++) acc[i] = 0ull;

    for (int ch = 0; ch < 14; ch++) {
        if (ch < 13) CPWAIT(1); else CPWAIT(0);
        __syncthreads();
        if (ch + 2 < 14) { issue(ch + 2); CPCOMMIT(); }
        const float* xb = sm + XS + (ch % 3) * 4096;
        const float* wb = sm + WS + (ch % 3) * 1024;
        #pragma unroll
        for (int kk = 0; kk < 16; kk++) {
            float4 xv = *reinterpret_cast<const float4*>(xb + kk * 256 + vbase + lane * 4);
            unsigned long long xq0, xq1, xq2, xq3;
            BCAST(xq0, xv.x); BCAST(xq1, xv.y); BCAST(xq2, xv.z); BCAST(xq3, xv.w);
            const ulonglong2* wp =
                reinterpret_cast<const ulonglong2*>(wb + kk * 64 + obase);
            ulonglong2 wA = wp[0], wB = wp[1], wC = wp[2], wD = wp[3];
            FMA2(acc[0],  wA.x, xq0); FMA2(acc[1],  wA.x, xq1);
            FMA2(acc[2],  wA.x, xq2); FMA2(acc[3],  wA.x, xq3);
            FMA2(acc[4],  wA.y, xq0); FMA2(acc[5],  wA.y, xq1);
            FMA2(acc[6],  wA.y, xq2); FMA2(acc[7],  wA.y, xq3);
            FMA2(acc[8],  wB.x, xq0); FMA2(acc[9],  wB.x, xq1);
            FMA2(acc[10], wB.x, xq2); FMA2(acc[11], wB.x, xq3);
            FMA2(acc[12], wB.y, xq0); FMA2(acc[13], wB.y, xq1);
            FMA2(acc[14], wB.y, xq2); FMA2(acc[15], wB.y, xq3);
            FMA2(acc[16], wC.x, xq0); FMA2(acc[17], wC.x, xq1);
            FMA2(acc[18], wC.x, xq2); FMA2(acc[19], wC.x, xq3);
            FMA2(acc[20], wC.y, xq0); FMA2(acc[21], wC.y, xq1);
            FMA2(acc[22], wC.y, xq2); FMA2(acc[23], wC.y, xq3);
            FMA2(acc[24], wD.x, xq0); FMA2(acc[25], wD.x, xq1);
            FMA2(acc[26], wD.x, xq2); FMA2(acc[27], wD.x, xq3);
            FMA2(acc[28], wD.y, xq0); FMA2(acc[29], wD.y, xq1);
            FMA2(acc[30], wD.y, xq2); FMA2(acc[31], wD.y, xq3);
        }
    }
    __syncthreads();   // ring dead -> HSO region may be written

    // acc[j*4+q] = outputs (obase+2j, +1), voxel vbase+lane*4+q -> HSO rows
    #pragma unroll
    for (int j = 0; j < 8; j++) {
        float lo0, hi0, lo1, hi1, lo2, hi2, lo3, hi3;
        UNPK(lo0, hi0, acc[j * 4 + 0]); UNPK(lo1, hi1, acc[j * 4 + 1]);
        UNPK(lo2, hi2, acc[j * 4 + 2]); UNPK(lo3, hi3, acc[j * 4 + 3]);
        int o = obase + 2 * j;
        *reinterpret_cast<float4*>(sm + HSO + o * 260 + vbase + lane * 4)
            = make_float4(lo0, lo1, lo2, lo3);
        *reinterpret_cast<float4*>(sm + HSO + (o + 1) * 260 + vbase + lane * 4)
            = make_float4(hi0, hi1, hi2, hi3);
    }
    __syncthreads();

    // ---- stage 2: fully per-thread, v = tid, all 32 outputs ----
    const int v = tid;

    float hv[32];
    #pragma unroll
    for (int jj = 0; jj < 32; jj++) {
        float tv = sm[HSO + jj * 260 + v] + sm[SWB + jj];
        hv[jj] = tv > 0.f ? tv : 0.2f * tv;
    }

    unsigned long long m2[16];
    {
        const unsigned long long* bmp =
            reinterpret_cast<const unsigned long long*>(sm + SWB + 64);
        #pragma unroll
        for (int p = 0; p < 16; p++) m2[p] = bmp[p];
    }
    #pragma unroll
    for (int jj = 0; jj < 32; jj++) {
        unsigned long long xj; BCAST(xj, hv[jj]);
        const unsigned long long* wr =
            reinterpret_cast<const unsigned long long*>(sm + SWB + 128 + jj * 32);
        #pragma unroll
        for (int p = 0; p < 16; p++) FMA2(m2[p], wr[p], xj);
    }
    float h2[32];
    #pragma unroll
    for (int p = 0; p < 16; p++) {
        float lo, hi; UNPK(lo, hi, m2[p]);
        h2[2 * p]     = lo > 0.f ? lo : 0.2f * lo;
        h2[2 * p + 1] = hi > 0.f ? hi : 0.2f * hi;
    }

    unsigned long long f[16];
    {
        const unsigned long long* bop =
            reinterpret_cast<const unsigned long long*>(sm + SWB + 96);
        #pragma unroll
        for (int p = 0; p < 16; p++) f[p] = bop[p];
    }
    #pragma unroll
    for (int i = 0; i < 32; i++) {
        unsigned long long xi; BCAST(xi, h2[i]);
        const unsigned long long* wr =
            reinterpret_cast<const unsigned long long*>(sm + SWB + 1152 + i * 32);
        #pragma unroll
        for (int p = 0; p < 16; p++) FMA2(f[p], wr[p], xi);
    }

    float* st = g_state + ((size_t)(b * NC) << 15) + v0 + v;
    if (!last) {
        #pragma unroll
        for (int p = 0; p < 16; p++) {
            float t0, t1; UNPK(t0, t1, f[p]);
            int o = 2 * p;
            float s0 = sm[HSO + (32 + o) * 260 + v] + sm[SWB + 32 + o];
            float s1 = sm[HSO + (33 + o) * 260 + v] + sm[SWB + 33 + o];
            st[(size_t)o << 15]       += 0.1f * (t0 + s0);
            st[(size_t)(o + 1) << 15] += 0.1f * (t1 + s1);
        }
    } else {
        float sum = 0.f;
        #pragma unroll
        for (int p = 0; p < 16; p++) {
            float t0, t1; UNPK(t0, t1, f[p]);
            int o = 2 * p;
            float s0 = sm[HSO + (32 + o) * 260 + v] + sm[SWB + 32 + o];
            float s1 = sm[HSO + (33 + o) * 260 + v] + sm[SWB + 33 + o];
            sum += st[(size_t)o << 15]       + 0.1f * (t0 + s0);
            sum += st[(size_t)(o + 1) << 15] + 0.1f * (t1 + s1);
        }
        out[b * VOL + v0 + v] = sum * (1.f / 32.f);
    }
}

// ---------------- launch ----------------

extern "C" void kernel_launch(void* const* d_in, const int* in_sizes, int n_in,
                              void* d_out, int out_size) {
    const float* z  = (const float*)d_in[0];
    const int*   y  = (const int*)d_in[1];
    const float* hw = (const float*)d_in[2];
    const float* hb = (const float*)d_in[3];
    float* out = (float*)d_out;
    (void)in_sizes; (void)n_in; (void)out_size;

    cudaFuncSetAttribute(k_residual, cudaFuncAttributeMaxDynamicSharedMemorySize,
                         SM_FLOATS * 4);

    k_init<<<dim3(128, 4), 256>>>(z);
    for (int it = 0; it < 4; it++) {
        k_sobel<<<dim3(32, 4), 512>>>();
        k_fold<<<4, 256>>>(y, hw, hb);
        k_residual<<<dim3(128, 4), 256, SM_FLOATS * 4>>>(out, it == 3 ? 1 : 0);
    }
}

// round 12
// speedup vs baseline: 1.1453x; 1.1453x over previous
#include <cuda_runtime.h>
#include <cuda_bf16.h>
#include <cstdint>

#define BATCH 4
#define NC 32
#define CIN 224
#define VOL 32768
#define KT 16512

__device__ float  g_state[BATCH * NC * VOL];
__device__ float  g_feat [BATCH * CIN * VOL];
__device__ double g_sumd [BATCH * CIN];
__device__ double g_sqd  [BATCH * CIN];
__device__ float  g_w    [BATCH * KT];

// offsets (floats) inside per-batch g_w block
#define WC_OFF  0       // [224 k][64 o]: o 0..31 = W_in', 32..63 = W_sh'
#define B64_OFF 14336
#define WM_OFF  14400
#define BM_OFF  15424
#define WO_OFF  15456
#define BO_OFF  16480

#define FMA2(acc, w, x) asm("fma.rn.f32x2 %0, %1, %2, %0;" : "+l"(acc) : "l"(w), "l"(x))
#define BCAST(d, f)     asm("mov.b64 %0, {%1, %1};" : "=l"(d) : "f"(f))
#define UNPK(lo, hi, q) asm("mov.b64 {%0, %1}, %2;" : "=f"(lo), "=f"(hi) : "l"(q))
#define CPA16(dst, src) asm volatile("cp.async.cg.shared.global [%0], [%1], 16;" :: "r"(dst), "l"(src))
#define CPCOMMIT()      asm volatile("cp.async.commit_group;")
#define CPWAIT(n)       asm volatile("cp.async.wait_group %0;" :: "n"(n))

// ---------------- init (z-normalize inline) ----------------

__global__ void k_init(const float* __restrict__ z) {
    int b = blockIdx.y;
    int v = (blockIdx.x << 8) + threadIdx.x;
    float val = 0.f;
    if (blockIdx.x < 2) {
        __shared__ float sh[8];
        __shared__ float snorm;
        int t = threadIdx.x;
        float v0 = z[b * 512 + t], v1 = z[b * 512 + 256 + t];
        float s = v0 * v0 + v1 * v1;
        #pragma unroll
        for (int o = 16; o; o >>= 1) s += __shfl_down_sync(~0u, s, o);
        if ((t & 31) == 0) sh[t >> 5] = s;
        __syncthreads();
        if (t < 8) {
            float x = sh[t];
            #pragma unroll
            for (int o = 4; o; o >>= 1) x += __shfl_down_sync(0xffu, x, o);
            if (t == 0) snorm = fmaxf(sqrtf(x), 1e-12f);
        }
        __syncthreads();
        val = z[b * 512 + v] / snorm;
    }
    #pragma unroll
    for (int c = 0; c < NC; c++) g_state[((b * NC + c) << 15) + v] = val;
}

// ---------------- sobel (best-known R5) ----------------

__global__ void __launch_bounds__(512) k_sobel() {
    __shared__ float sl[2][4][36][32];
    __shared__ float red[16][14];
    const int c = blockIdx.x, b = blockIdx.y;
    const int tid = threadIdx.x;
    const int lane = tid & 31, wid = tid >> 5;
    const int h0 = wid * 2;
    const float* __restrict__ xin = g_state + ((size_t)(b * NC + c) << 15);
    float* __restrict__ featb = g_feat + (size_t)(b * CIN + c) * VOL;

    for (int i = tid; i < 1024; i += 512) {
        int w = i & 31, r = (i >> 5) & 3, arr = (i >> 7) & 3, bu = i >> 9;
        int hp = (r < 2) ? r : r + 32;
        sl[bu][arr][hp][w] = 0.f;
    }

    const float R2 = 0.70710678118654752f;
    const float S1 = 1.f + R2;

    float stat[14];
    #pragma unroll
    for (int i = 0; i < 14; i++) stat[i] = 0.f;
    float W[2][6][5];
    #pragma unroll
    for (int r = 0; r < 2; r++)
        #pragma unroll
        for (int a = 0; a < 6; a++)
            #pragma unroll
            for (int k = 0; k < 5; k++) W[r][a][k] = 0.f;

    float xc[2];
    xc[0] = xin[((h0 + 0) << 5) + lane];
    xc[1] = xin[((h0 + 1) << 5) + lane];

    __syncthreads();

    float sw3[2], dw3[2], sw5[2], dw5[2];

    #pragma unroll 2
    for (int s = 0; s < 34; s++) {
        const int bu = s & 1;
        float xn0 = 0.f, xn1 = 0.f;
        if (s + 1 < 32) {
            xn0 = xin[((s + 1) << 10) + ((h0 + 0) << 5) + lane];
            xn1 = xin[((s + 1) << 10) + ((h0 + 1) << 5) + lane];
        }
        if (s < 32) {
            #pragma unroll
            for (int r = 0; r < 2; r++) {
                float xv = xc[r];
                stat[0] += xv; stat[1] += xv * xv;
                float xm1 = __shfl_up_sync(~0u, xv, 1);   if (lane == 0)  xm1 = 0.f;
                float xm2 = __shfl_up_sync(~0u, xv, 2);   if (lane < 2)   xm2 = 0.f;
                float xp1 = __shfl_down_sync(~0u, xv, 1); if (lane == 31) xp1 = 0.f;
                float xp2 = __shfl_down_sync(~0u, xv, 2); if (lane > 29)  xp2 = 0.f;
                sw3[r] = xm1 + 2.f * xv + xp1;
                dw3[r] = xp1 - xm1;
                sw5[r] = xm2 + xp2 + S1 * (xm1 + xp1) + 2.f * xv;
                dw5[r] = (xp2 - xm2) + R2 * (xp1 - xm1);
                int hp = h0 + r + 2;
                sl[bu][0][hp][lane] = sw3[r];
                sl[bu][1][hp][lane] = dw3[r];
                sl[bu][2][hp][lane] = sw5[r];
                sl[bu][3][hp][lane] = dw5[r];
            }
        }
        xc[0] = xn0; xc[1] = xn1;
        __syncthreads();
        #pragma unroll
        for (int r = 0; r < 2; r++) {
            float a30, a31, a32, a50, a51, a52;
            if (s < 32) {
                int hp = h0 + r + 2;
                float s3m = sl[bu][0][hp - 1][lane], s3p = sl[bu][0][hp + 1][lane];
                float d3m = sl[bu][1][hp - 1][lane], d3p = sl[bu][1][hp + 1][lane];
                float s5m2 = sl[bu][2][hp - 2][lane], s5m1 = sl[bu][2][hp - 1][lane];
                float s5p1 = sl[bu][2][hp + 1][lane], s5p2 = sl[bu][2][hp + 2][lane];
                float d5m2 = sl[bu][3][hp - 2][lane], d5m1 = sl[bu][3][hp - 1][lane];
                float d5p1 = sl[bu][3][hp + 1][lane], d5p2 = sl[bu][3][hp + 2][lane];
                a30 = d3m + 2.f * dw3[r] + d3p;
                a31 = s3p - s3m;
                a32 = s3m + 2.f * sw3[r] + s3p;
                a50 = d5m2 + d5p2 + S1 * (d5m1 + d5p1) + 2.f * dw5[r];
                a51 = (s5p2 - s5m2) + R2 * (s5p1 - s5m1);
                a52 = s5m2 + s5p2 + S1 * (s5m1 + s5p1) + 2.f * sw5[r];
            } else {
                a30 = a31 = a32 = a50 = a51 = a52 = 0.f;
            }
            #pragma unroll
            for (int a = 0; a < 6; a++) {
                W[r][a][0] = W[r][a][1]; W[r][a][1] = W[r][a][2];
                W[r][a][2] = W[r][a][3]; W[r][a][3] = W[r][a][4];
            }
            W[r][0][4] = a32; W[r][1][4] = a31; W[r][2][4] = a30;
            W[r][3][4] = a52; W[r][4][4] = a51; W[r][5][4] = a50;

            if (s >= 2) {
                int dc = s - 2;
                float o1 = W[r][0][3] - W[r][0][1];
                float o2 = W[r][1][1] + 2.f * W[r][1][2] + W[r][1][3];
                float o3 = W[r][2][1] + 2.f * W[r][2][2] + W[r][2][3];
                float o4 = (W[r][3][4] - W[r][3][0]) + R2 * (W[r][3][3] - W[r][3][1]);
                float o5 = W[r][4][0] + W[r][4][4] + S1 * (W[r][4][1] + W[r][4][3]) + 2.f * W[r][4][2];
                float o6 = W[r][5][0] + W[r][5][4] + S1 * (W[r][5][1] + W[r][5][3]) + 2.f * W[r][5][2];
                int v = (dc << 10) + ((h0 + r) << 5) + lane;
                featb[(size_t)32 * VOL + v]  = o1;
                featb[(size_t)64 * VOL + v]  = o2;
                featb[(size_t)96 * VOL + v]  = o3;
                featb[(size_t)128 * VOL + v] = o4;
                featb[(size_t)160 * VOL + v] = o5;
                featb[(size_t)192 * VOL + v] = o6;
                stat[2]  += o1; stat[3]  += o1 * o1;
                stat[4]  += o2; stat[5]  += o2 * o2;
                stat[6]  += o3; stat[7]  += o3 * o3;
                stat[8]  += o4; stat[9]  += o4 * o4;
                stat[10] += o5; stat[11] += o5 * o5;
                stat[12] += o6; stat[13] += o6 * o6;
            }
        }
    }

    #pragma unroll
    for (int i = 0; i < 14; i++) {
        float v = stat[i];
        #pragma unroll
        for (int o = 16; o; o >>= 1) v += __shfl_down_sync(~0u, v, o);
        stat[i] = v;
    }
    if (lane == 0)
        #pragma unroll
        for (int i = 0; i < 14; i++) red[wid][i] = stat[i];
    __syncthreads();
    if (tid < 14) {
        double acc = 0.0;
        #pragma unroll
        for (int k = 0; k < 16; k++) acc += (double)red[k][tid];
        int g = tid >> 1;
        if (tid & 1) g_sqd [b * CIN + g * 32 + c] = acc;
        else         g_sumd[b * CIN + g * 32 + c] = acc;
    }
}

// ---------------- fold norm into weights (theta inlined) ----------------

__global__ void k_fold(const int* __restrict__ y, const float* __restrict__ hw,
                       const float* __restrict__ hb) {
    int b = blockIdx.x, tid = threadIdx.x;
    int lane = tid & 31, wid = tid >> 5;
    __shared__ float smean[CIN], srs[CIN];
    if (tid < CIN) {
        double m = g_sumd[b * CIN + tid] * (1.0 / 32768.0);
        double var = g_sqd[b * CIN + tid] * (1.0 / 32768.0) - m * m;
        smean[tid] = (float)m;
        srs[tid] = (float)rsqrt(var + 1e-5);
    }
    __syncthreads();
    const float* th = hw + (size_t)y[b] * KT;
    float* w = g_w + b * KT;
    #pragma unroll
    for (int j = 0; j < 8; j++) {
        int o = wid * 8 + j;
        int off = (o < 32) ? o * 224 : 9312 + (o - 32) * 224;
        float corr = 0.f;
        #pragma unroll
        for (int q = 0; q < 7; q++) {
            int cc = lane + q * 32;
            float wv = (th[off + cc] + hb[off + cc]) * srs[cc];
            w[WC_OFF + cc * 64 + o] = wv;
            corr += wv * smean[cc];
        }
        #pragma unroll
        for (int d = 16; d; d >>= 1) corr += __shfl_down_sync(~0u, corr, d);
        if (lane == 0) {
            float braw = (o < 32) ? (th[7168 + o] + hb[7168 + o])
                                  : (th[16480 + o - 32] + hb[16480 + o - 32]);
            w[B64_OFF + o] = braw - corr;
        }
    }
    for (int i = tid; i < 1024; i += 256) {
        int r = i >> 5, cc = i & 31;
        w[WM_OFF + cc * 32 + r] = th[7200 + r * 32 + cc] + hb[7200 + r * 32 + cc];
        w[WO_OFF + cc * 32 + r] = th[8256 + r * 32 + cc] + hb[8256 + r * 32 + cc];
    }
    if (tid < 32) {
        w[BM_OFF + tid] = th[8224 + tid] + hb[8224 + tid];
        w[BO_OFF + tid] = th[9280 + tid] + hb[9280 + tid];
    }
}

// ---------------- register-blocked residual MLP (R10 config, 3 blocks/SM) ---
// block: 64 outputs x 128 voxels, 256 threads; thread = 8 out x 4 vox
// 16-channel chunks, 3-buffer cp.async ring, 1 barrier per chunk.
// Last iteration fuses the channel mean (skips state write-back).
#define XS   0       // [3][16][128] = 6144
#define WS   6144    // [3][16][64]  = 3072
#define HSO  0       // [64][132] = 8448 (union over XS/WS after stage 1)
#define SWB  9216    // b64[64] | bm[32] | bo[32] | wm[1024] | wo[1024] = 2176
#define H2S  11392   // [32][129] = 4128
#define SM_FLOATS 15520

__global__ void __launch_bounds__(256, 3) k_residual(float* __restrict__ out, int last) {
    extern __shared__ float sm[];
    const int tid = threadIdx.x;
    const int wid = tid >> 5, lane = tid & 31;
    const int b = blockIdx.y;
    const int v0 = blockIdx.x << 7;
    const float* gw = g_w + b * KT;
    unsigned swa = (unsigned)__cvta_generic_to_shared(sm);

    if (tid < 64)  sm[SWB + tid]       = gw[B64_OFF + tid];
    if (tid < 32)  sm[SWB + 64 + tid]  = gw[BM_OFF + tid];
    if (tid >= 32 && tid < 64) sm[SWB + 96 + (tid - 32)] = gw[BO_OFF + tid - 32];
    for (int i = tid; i < 1024; i += 256) sm[SWB + 128 + i]  = gw[WM_OFF + i];
    for (int i = tid; i < 1024; i += 256) sm[SWB + 1152 + i] = gw[WO_OFF + i];

    const int xrow0 = tid >> 5, clw = tid & 31;
    auto issue = [&](int ch) {
        int slot = ch % 3;
        int cc0 = ch * 16 + xrow0;
        const float* xsrc0 = (cc0 < 32)
            ? g_state + ((size_t)(b * NC + cc0) << 15) + v0 + clw * 4
            : g_feat  + ((size_t)(b * CIN + cc0) << 15) + v0 + clw * 4;
        CPA16(swa + (XS + slot * 2048 + xrow0 * 128 + clw * 4) * 4, xsrc0);
        int cc1 = cc0 + 8;
        const float* xsrc1 = (cc1 < 32)
            ? g_state + ((size_t)(b * NC + cc1) << 15) + v0 + clw * 4
            : g_feat  + ((size_t)(b * CIN + cc1) << 15) + v0 + clw * 4;
        CPA16(swa + (XS + slot * 2048 + (xrow0 + 8) * 128 + clw * 4) * 4, xsrc1);
        const float* wsrc = gw + WC_OFF + ch * 1024 + tid * 4;
        CPA16(swa + (WS + slot * 1024 + tid * 4) * 4, wsrc);
    };

    issue(0); CPCOMMIT();
    issue(1); CPCOMMIT();

    unsigned long long acc[16];
    #pragma unroll
    for (int i = 0; i < 16; i++) acc[i] = 0ull;

    for (int ch = 0; ch < 14; ch++) {
        if (ch < 13) CPWAIT(1); else CPWAIT(0);
        __syncthreads();
        if (ch + 2 < 14) { issue(ch + 2); CPCOMMIT(); }
        const float* xb = sm + XS + (ch % 3) * 2048;
        const float* wb = sm + WS + (ch % 3) * 1024;
        #pragma unroll
        for (int kk = 0; kk < 16; kk++) {
            float4 xv = *reinterpret_cast<const float4*>(xb + kk * 128 + lane * 4);
            unsigned long long xq0, xq1, xq2, xq3;
            BCAST(xq0, xv.x); BCAST(xq1, xv.y); BCAST(xq2, xv.z); BCAST(xq3, xv.w);
            const ulonglong2* wp =
                reinterpret_cast<const ulonglong2*>(wb + kk * 64 + wid * 8);
            ulonglong2 wA = wp[0], wB = wp[1];
            FMA2(acc[0],  wA.x, xq0); FMA2(acc[1],  wA.x, xq1);
            FMA2(acc[2],  wA.x, xq2); FMA2(acc[3],  wA.x, xq3);
            FMA2(acc[4],  wA.y, xq0); FMA2(acc[5],  wA.y, xq1);
            FMA2(acc[6],  wA.y, xq2); FMA2(acc[7],  wA.y, xq3);
            FMA2(acc[8],  wB.x, xq0); FMA2(acc[9],  wB.x, xq1);
            FMA2(acc[10], wB.x, xq2); FMA2(acc[11], wB.x, xq3);
            FMA2(acc[12], wB.y, xq0); FMA2(acc[13], wB.y, xq1);
            FMA2(acc[14], wB.y, xq2); FMA2(acc[15], wB.y, xq3);
        }
    }
    __syncthreads();   // ring dead -> HSO region may be written

    #pragma unroll
    for (int j = 0; j < 4; j++) {
        float lo0, hi0, lo1, hi1, lo2, hi2, lo3, hi3;
        UNPK(lo0, hi0, acc[j * 4 + 0]); UNPK(lo1, hi1, acc[j * 4 + 1]);
        UNPK(lo2, hi2, acc[j * 4 + 2]); UNPK(lo3, hi3, acc[j * 4 + 3]);
        int o = wid * 8 + 2 * j;
        *reinterpret_cast<float4*>(sm + HSO + o * 132 + lane * 4)
            = make_float4(lo0, lo1, lo2, lo3);
        *reinterpret_cast<float4*>(sm + HSO + (o + 1) * 132 + lane * 4)
            = make_float4(hi0, hi1, hi2, hi3);
    }
    __syncthreads();

    // ---- stage 2 (per voxel, two 32x32 GEMMs; stage-1 biases added here) ----
    const int v = tid & 127, half = tid >> 7;
    const int obase = half * 16;

    float hv[32];
    #pragma unroll
    for (int jj = 0; jj < 32; jj++) {
        float tv = sm[HSO + jj * 132 + v] + sm[SWB + jj];
        hv[jj] = tv > 0.f ? tv : 0.2f * tv;
    }

    unsigned long long m2[8];
    {
        const unsigned long long* bmp =
            reinterpret_cast<const unsigned long long*>(sm + SWB + 64 + obase);
        #pragma unroll
        for (int p = 0; p < 8; p++) m2[p] = bmp[p];
    }
    #pragma unroll
    for (int jj = 0; jj < 32; jj++) {
        unsigned long long xj; BCAST(xj, hv[jj]);
        const unsigned long long* wr =
            reinterpret_cast<const unsigned long long*>(sm + SWB + 128 + jj * 32 + obase);
        #pragma unroll
        for (int p = 0; p < 8; p++) FMA2(m2[p], wr[p], xj);
    }
    #pragma unroll
    for (int p = 0; p < 8; p++) {
        float lo, hi; UNPK(lo, hi, m2[p]);
        lo = lo > 0.f ? lo : 0.2f * lo;
        hi = hi > 0.f ? hi : 0.2f * hi;
        sm[H2S + (obase + 2 * p) * 129 + v]     = lo;
        sm[H2S + (obase + 2 * p + 1) * 129 + v] = hi;
    }
    __syncthreads();

    unsigned long long f[8];
    {
        const unsigned long long* bop =
            reinterpret_cast<const unsigned long long*>(sm + SWB + 96 + obase);
        #pragma unroll
        for (int p = 0; p < 8; p++) f[p] = bop[p];
    }
    #pragma unroll
    for (int i = 0; i < 32; i++) {
        float h2 = sm[H2S + i * 129 + v];
        unsigned long long xi; BCAST(xi, h2);
        const unsigned long long* wr =
            reinterpret_cast<const unsigned long long*>(sm + SWB + 1152 + i * 32 + obase);
        #pragma unroll
        for (int p = 0; p < 8; p++) FMA2(f[p], wr[p], xi);
    }

    float* st = g_state + ((size_t)(b * NC) << 15) + v0 + v;
    if (!last) {
        #pragma unroll
        for (int p = 0; p < 8; p++) {
            float t0, t1; UNPK(t0, t1, f[p]);
            int o = obase + 2 * p;
            float s0 = sm[HSO + (32 + o) * 132 + v] + sm[SWB + 32 + o];
            float s1 = sm[HSO + (33 + o) * 132 + v] + sm[SWB + 33 + o];
            st[(size_t)o << 15]       += 0.1f * (t0 + s0);
            st[(size_t)(o + 1) << 15] += 0.1f * (t1 + s1);
        }
    } else {
        // fused channel mean: halves combine through dead H2S region
        float psum = 0.f;
        #pragma unroll
        for (int p = 0; p < 8; p++) {
            float t0, t1; UNPK(t0, t1, f[p]);
            int o = obase + 2 * p;
            float s0 = sm[HSO + (32 + o) * 132 + v] + sm[SWB + 32 + o];
            float s1 = sm[HSO + (33 + o) * 132 + v] + sm[SWB + 33 + o];
            psum += st[(size_t)o << 15]       + 0.1f * (t0 + s0);
            psum += st[(size_t)(o + 1) << 15] + 0.1f * (t1 + s1);
        }
        __syncthreads();
        if (half == 1) sm[H2S + v] = psum;
        __syncthreads();
        if (half == 0)
            out[b * VOL + v0 + v] = (psum + sm[H2S + v]) * (1.f / 32.f);
    }
}

// ---------------- launch ----------------

extern "C" void kernel_launch(void* const* d_in, const int* in_sizes, int n_in,
                              void* d_out, int out_size) {
    const float* z  = (const float*)d_in[0];
    const int*   y  = (const int*)d_in[1];
    const float* hw = (const float*)d_in[2];
    const float* hb = (const float*)d_in[3];
    float* out = (float*)d_out;
    (void)in_sizes; (void)n_in; (void)out_size;

    cudaFuncSetAttribute(k_residual, cudaFuncAttributeMaxDynamicSharedMemorySize,
                         SM_FLOATS * 4);

    k_init<<<dim3(128, 4), 256>>>(z);
    for (int it = 0; it < 4; it++) {
        k_sobel<<<dim3(32, 4), 512>>>();
        k_fold<<<4, 256>>>(y, hw, hb);
        k_residual<<<dim3(256, 4), 256, SM_FLOATS * 4>>>(out, it == 3 ? 1 : 0);
    }
}

// round 13
// speedup vs baseline: 1.2464x; 1.0883x over previous
#include <cuda_runtime.h>
#include <cuda_bf16.h>
#include <cstdint>

#define BATCH 4
#define NC 32
#define CIN 224
#define VOL 32768
#define KT 16512

__device__ float  g_state[BATCH * NC * VOL];
__device__ float  g_feat [BATCH * CIN * VOL];
__device__ double g_sumd [BATCH * CIN];
__device__ double g_sqd  [BATCH * CIN];
__device__ float  g_w    [BATCH * KT];

// offsets (floats) inside per-batch g_w block
#define WC_OFF  0       // [224 k][64 o]: o 0..31 = W_in', 32..63 = W_sh'
#define B64_OFF 14336
#define WM_OFF  14400
#define BM_OFF  15424
#define WO_OFF  15456
#define BO_OFF  16480

#define FMA2(acc, w, x) asm("fma.rn.f32x2 %0, %1, %2, %0;" : "+l"(acc) : "l"(w), "l"(x))
#define BCAST(d, f)     asm("mov.b64 %0, {%1, %1};" : "=l"(d) : "f"(f))
#define UNPK(lo, hi, q) asm("mov.b64 {%0, %1}, %2;" : "=f"(lo), "=f"(hi) : "l"(q))
#define CPA16(dst, src) asm volatile("cp.async.cg.shared.global [%0], [%1], 16;" :: "r"(dst), "l"(src))
#define CPCOMMIT()      asm volatile("cp.async.commit_group;")
#define CPWAIT(n)       asm volatile("cp.async.wait_group %0;" :: "n"(n))

// ---------------- init (z-normalize inline) ----------------

__global__ void k_init(const float* __restrict__ z) {
    int b = blockIdx.y;
    int v = (blockIdx.x << 8) + threadIdx.x;
    float val = 0.f;
    if (blockIdx.x < 2) {
        __shared__ float sh[8];
        __shared__ float snorm;
        int t = threadIdx.x;
        float v0 = z[b * 512 + t], v1 = z[b * 512 + 256 + t];
        float s = v0 * v0 + v1 * v1;
        #pragma unroll
        for (int o = 16; o; o >>= 1) s += __shfl_down_sync(~0u, s, o);
        if ((t & 31) == 0) sh[t >> 5] = s;
        __syncthreads();
        if (t < 8) {
            float x = sh[t];
            #pragma unroll
            for (int o = 4; o; o >>= 1) x += __shfl_down_sync(0xffu, x, o);
            if (t == 0) snorm = fmaxf(sqrtf(x), 1e-12f);
        }
        __syncthreads();
        val = z[b * 512 + v] / snorm;
    }
    #pragma unroll
    for (int c = 0; c < NC; c++) g_state[((b * NC + c) << 15) + v] = val;
}

// ---------------- sobel: 1024 threads, 1 h-row per thread ----------------

__global__ void __launch_bounds__(1024) k_sobel() {
    __shared__ float sl[2][4][36][32];   // [buf][arr][h+2][w]
    __shared__ float red[32][14];
    const int c = blockIdx.x, b = blockIdx.y;
    const int tid = threadIdx.x;
    const int lane = tid & 31, wid = tid >> 5;   // wid = h row
    const float* __restrict__ xin = g_state + ((size_t)(b * NC + c) << 15);
    float* __restrict__ featb = g_feat + (size_t)(b * CIN + c) * VOL;

    // zero h pad rows (0,1,34,35) in both buffers, all 4 arrays
    {
        int i = tid;
        int w = i & 31, r = (i >> 5) & 3, arr = (i >> 7) & 3, bu = i >> 9;
        int hp = (r < 2) ? r : r + 32;
        sl[bu][arr][hp][w] = 0.f;
    }

    const float R2 = 0.70710678118654752f;
    const float S1 = 1.f + R2;

    float stat[14];
    #pragma unroll
    for (int i = 0; i < 14; i++) stat[i] = 0.f;
    float W3[3][4], W5[3][5];
    #pragma unroll
    for (int a = 0; a < 3; a++) {
        #pragma unroll
        for (int k = 0; k < 4; k++) W3[a][k] = 0.f;
        #pragma unroll
        for (int k = 0; k < 5; k++) W5[a][k] = 0.f;
    }

    float xc = xin[(wid << 5) + lane];
    const int hp = wid + 2;

    __syncthreads();

    #pragma unroll 2
    for (int s = 0; s < 34; s++) {
        const int bu = s & 1;
        float xn = 0.f;
        if (s + 1 < 32) xn = xin[((s + 1) << 10) + (wid << 5) + lane];
        float sw3, dw3, sw5, dw5;
        if (s < 32) {
            float xv = xc;
            stat[0] += xv; stat[1] += xv * xv;
            float xm1 = __shfl_up_sync(~0u, xv, 1);   if (lane == 0)  xm1 = 0.f;
            float xm2 = __shfl_up_sync(~0u, xv, 2);   if (lane < 2)   xm2 = 0.f;
            float xp1 = __shfl_down_sync(~0u, xv, 1); if (lane == 31) xp1 = 0.f;
            float xp2 = __shfl_down_sync(~0u, xv, 2); if (lane > 29)  xp2 = 0.f;
            sw3 = xm1 + 2.f * xv + xp1;
            dw3 = xp1 - xm1;
            sw5 = xm2 + xp2 + S1 * (xm1 + xp1) + 2.f * xv;
            dw5 = (xp2 - xm2) + R2 * (xp1 - xm1);
            sl[bu][0][hp][lane] = sw3;
            sl[bu][1][hp][lane] = dw3;
            sl[bu][2][hp][lane] = sw5;
            sl[bu][3][hp][lane] = dw5;
        }
        xc = xn;
        __syncthreads();
        float a30, a31, a32, a50, a51, a52;
        if (s < 32) {
            float s3m = sl[bu][0][hp - 1][lane], s3p = sl[bu][0][hp + 1][lane];
            float d3m = sl[bu][1][hp - 1][lane], d3p = sl[bu][1][hp + 1][lane];
            float s5m2 = sl[bu][2][hp - 2][lane], s5m1 = sl[bu][2][hp - 1][lane];
            float s5p1 = sl[bu][2][hp + 1][lane], s5p2 = sl[bu][2][hp + 2][lane];
            float d5m2 = sl[bu][3][hp - 2][lane], d5m1 = sl[bu][3][hp - 1][lane];
            float d5p1 = sl[bu][3][hp + 1][lane], d5p2 = sl[bu][3][hp + 2][lane];
            a30 = d3m + 2.f * dw3 + d3p;
            a31 = s3p - s3m;
            a32 = s3m + 2.f * sw3 + s3p;
            a50 = d5m2 + d5p2 + S1 * (d5m1 + d5p1) + 2.f * dw5;
            a51 = (s5p2 - s5m2) + R2 * (s5p1 - s5m1);
            a52 = s5m2 + s5p2 + S1 * (s5m1 + s5p1) + 2.f * sw5;
        } else {
            a30 = a31 = a32 = a50 = a51 = a52 = 0.f;
        }
        // shift windows; W3 4-deep (holds s-3..s after push), W5 5-deep (s-4..s)
        #pragma unroll
        for (int a = 0; a < 3; a++) {
            W3[a][0] = W3[a][1]; W3[a][1] = W3[a][2]; W3[a][2] = W3[a][3];
            W5[a][0] = W5[a][1]; W5[a][1] = W5[a][2];
            W5[a][2] = W5[a][3]; W5[a][3] = W5[a][4];
        }
        W3[0][3] = a32; W3[1][3] = a31; W3[2][3] = a30;
        W5[0][4] = a52; W5[1][4] = a51; W5[2][4] = a50;

        if (s >= 2) {
            int dc = s - 2;
            float o1 = W3[0][2] - W3[0][0];
            float o2 = W3[1][0] + 2.f * W3[1][1] + W3[1][2];
            float o3 = W3[2][0] + 2.f * W3[2][1] + W3[2][2];
            float o4 = (W5[0][4] - W5[0][0]) + R2 * (W5[0][3] - W5[0][1]);
            float o5 = W5[1][0] + W5[1][4] + S1 * (W5[1][1] + W5[1][3]) + 2.f * W5[1][2];
            float o6 = W5[2][0] + W5[2][4] + S1 * (W5[2][1] + W5[2][3]) + 2.f * W5[2][2];
            int v = (dc << 10) + (wid << 5) + lane;
            featb[(size_t)32 * VOL + v]  = o1;
            featb[(size_t)64 * VOL + v]  = o2;
            featb[(size_t)96 * VOL + v]  = o3;
            featb[(size_t)128 * VOL + v] = o4;
            featb[(size_t)160 * VOL + v] = o5;
            featb[(size_t)192 * VOL + v] = o6;
            stat[2]  += o1; stat[3]  += o1 * o1;
            stat[4]  += o2; stat[5]  += o2 * o2;
            stat[6]  += o3; stat[7]  += o3 * o3;
            stat[8]  += o4; stat[9]  += o4 * o4;
            stat[10] += o5; stat[11] += o5 * o5;
            stat[12] += o6; stat[13] += o6 * o6;
        }
    }

    #pragma unroll
    for (int i = 0; i < 14; i++) {
        float v = stat[i];
        #pragma unroll
        for (int o = 16; o; o >>= 1) v += __shfl_down_sync(~0u, v, o);
        stat[i] = v;
    }
    if (lane == 0)
        #pragma unroll
        for (int i = 0; i < 14; i++) red[wid][i] = stat[i];
    __syncthreads();
    if (tid < 14) {
        double acc = 0.0;
        #pragma unroll
        for (int k = 0; k < 32; k++) acc += (double)red[k][tid];
        int g = tid >> 1;
        if (tid & 1) g_sqd [b * CIN + g * 32 + c] = acc;
        else         g_sumd[b * CIN + g * 32 + c] = acc;
    }
}

// -------- fold norm into weights: grid (4 batches, 4 parts) --------

__global__ void k_fold(const int* __restrict__ y, const float* __restrict__ hw,
                       const float* __restrict__ hb) {
    int b = blockIdx.x, part = blockIdx.y, tid = threadIdx.x;
    int lane = tid & 31, wid = tid >> 5;
    __shared__ float smean[CIN], srs[CIN];
    if (tid < CIN) {
        double m = g_sumd[b * CIN + tid] * (1.0 / 32768.0);
        double var = g_sqd[b * CIN + tid] * (1.0 / 32768.0) - m * m;
        smean[tid] = (float)m;
        srs[tid] = (float)rsqrt(var + 1e-5);
    }
    __syncthreads();
    const float* th = hw + (size_t)y[b] * KT;
    float* w = g_w + b * KT;
    #pragma unroll
    for (int j = 0; j < 2; j++) {
        int o = part * 16 + wid * 2 + j;
        int off = (o < 32) ? o * 224 : 9312 + (o - 32) * 224;
        float corr = 0.f;
        #pragma unroll
        for (int q = 0; q < 7; q++) {
            int cc = lane + q * 32;
            float wv = (th[off + cc] + hb[off + cc]) * srs[cc];
            w[WC_OFF + cc * 64 + o] = wv;
            corr += wv * smean[cc];
        }
        #pragma unroll
        for (int d = 16; d; d >>= 1) corr += __shfl_down_sync(~0u, corr, d);
        if (lane == 0) {
            float braw = (o < 32) ? (th[7168 + o] + hb[7168 + o])
                                  : (th[16480 + o - 32] + hb[16480 + o - 32]);
            w[B64_OFF + o] = braw - corr;
        }
    }
    {
        int i = part * 256 + tid;
        int r = i >> 5, cc = i & 31;
        w[WM_OFF + cc * 32 + r] = th[7200 + r * 32 + cc] + hb[7200 + r * 32 + cc];
        w[WO_OFF + cc * 32 + r] = th[8256 + r * 32 + cc] + hb[8256 + r * 32 + cc];
    }
    if (part == 0 && tid < 32) {
        w[BM_OFF + tid] = th[8224 + tid] + hb[8224 + tid];
        w[BO_OFF + tid] = th[9280 + tid] + hb[9280 + tid];
    }
}

// ---------------- register-blocked residual MLP (R12 best) ----------------
#define XS   0       // [3][16][128] = 6144
#define WS   6144    // [3][16][64]  = 3072
#define HSO  0       // [64][132] = 8448 (union over XS/WS after stage 1)
#define SWB  9216    // b64[64] | bm[32] | bo[32] | wm[1024] | wo[1024] = 2176
#define H2S  11392   // [32][129] = 4128
#define SM_FLOATS 15520

__global__ void __launch_bounds__(256, 3) k_residual(float* __restrict__ out, int last) {
    extern __shared__ float sm[];
    const int tid = threadIdx.x;
    const int wid = tid >> 5, lane = tid & 31;
    const int b = blockIdx.y;
    const int v0 = blockIdx.x << 7;
    const float* gw = g_w + b * KT;
    unsigned swa = (unsigned)__cvta_generic_to_shared(sm);

    if (tid < 64)  sm[SWB + tid]       = gw[B64_OFF + tid];
    if (tid < 32)  sm[SWB + 64 + tid]  = gw[BM_OFF + tid];
    if (tid >= 32 && tid < 64) sm[SWB + 96 + (tid - 32)] = gw[BO_OFF + tid - 32];
    for (int i = tid; i < 1024; i += 256) sm[SWB + 128 + i]  = gw[WM_OFF + i];
    for (int i = tid; i < 1024; i += 256) sm[SWB + 1152 + i] = gw[WO_OFF + i];

    const int xrow0 = tid >> 5, clw = tid & 31;
    auto issue = [&](int ch) {
        int slot = ch % 3;
        int cc0 = ch * 16 + xrow0;
        const float* xsrc0 = (cc0 < 32)
            ? g_state + ((size_t)(b * NC + cc0) << 15) + v0 + clw * 4
            : g_feat  + ((size_t)(b * CIN + cc0) << 15) + v0 + clw * 4;
        CPA16(swa + (XS + slot * 2048 + xrow0 * 128 + clw * 4) * 4, xsrc0);
        int cc1 = cc0 + 8;
        const float* xsrc1 = (cc1 < 32)
            ? g_state + ((size_t)(b * NC + cc1) << 15) + v0 + clw * 4
            : g_feat  + ((size_t)(b * CIN + cc1) << 15) + v0 + clw * 4;
        CPA16(swa + (XS + slot * 2048 + (xrow0 + 8) * 128 + clw * 4) * 4, xsrc1);
        const float* wsrc = gw + WC_OFF + ch * 1024 + tid * 4;
        CPA16(swa + (WS + slot * 1024 + tid * 4) * 4, wsrc);
    };

    issue(0); CPCOMMIT();
    issue(1); CPCOMMIT();

    unsigned long long acc[16];
    #pragma unroll
    for (int i = 0; i < 16; i++) acc[i] = 0ull;

    for (int ch = 0; ch < 14; ch++) {
        if (ch < 13) CPWAIT(1); else CPWAIT(0);
        __syncthreads();
        if (ch + 2 < 14) { issue(ch + 2); CPCOMMIT(); }
        const float* xb = sm + XS + (ch % 3) * 2048;
        const float* wb = sm + WS + (ch % 3) * 1024;
        #pragma unroll
        for (int kk = 0; kk < 16; kk++) {
            float4 xv = *reinterpret_cast<const float4*>(xb + kk * 128 + lane * 4);
            unsigned long long xq0, xq1, xq2, xq3;
            BCAST(xq0, xv.x); BCAST(xq1, xv.y); BCAST(xq2, xv.z); BCAST(xq3, xv.w);
            const ulonglong2* wp =
                reinterpret_cast<const ulonglong2*>(wb + kk * 64 + wid * 8);
            ulonglong2 wA = wp[0], wB = wp[1];
            FMA2(acc[0],  wA.x, xq0); FMA2(acc[1],  wA.x, xq1);
            FMA2(acc[2],  wA.x, xq2); FMA2(acc[3],  wA.x, xq3);
            FMA2(acc[4],  wA.y, xq0); FMA2(acc[5],  wA.y, xq1);
            FMA2(acc[6],  wA.y, xq2); FMA2(acc[7],  wA.y, xq3);
            FMA2(acc[8],  wB.x, xq0); FMA2(acc[9],  wB.x, xq1);
            FMA2(acc[10], wB.x, xq2); FMA2(acc[11], wB.x, xq3);
            FMA2(acc[12], wB.y, xq0); FMA2(acc[13], wB.y, xq1);
            FMA2(acc[14], wB.y, xq2); FMA2(acc[15], wB.y, xq3);
        }
    }
    __syncthreads();   // ring dead -> HSO region may be written

    #pragma unroll
    for (int j = 0; j < 4; j++) {
        float lo0, hi0, lo1, hi1, lo2, hi2, lo3, hi3;
        UNPK(lo0, hi0, acc[j * 4 + 0]); UNPK(lo1, hi1, acc[j * 4 + 1]);
        UNPK(lo2, hi2, acc[j * 4 + 2]); UNPK(lo3, hi3, acc[j * 4 + 3]);
        int o = wid * 8 + 2 * j;
        *reinterpret_cast<float4*>(sm + HSO + o * 132 + lane * 4)
            = make_float4(lo0, lo1, lo2, lo3);
        *reinterpret_cast<float4*>(sm + HSO + (o + 1) * 132 + lane * 4)
            = make_float4(hi0, hi1, hi2, hi3);
    }
    __syncthreads();

    const int v = tid & 127, half = tid >> 7;
    const int obase = half * 16;

    float hv[32];
    #pragma unroll
    for (int jj = 0; jj < 32; jj++) {
        float tv = sm[HSO + jj * 132 + v] + sm[SWB + jj];
        hv[jj] = tv > 0.f ? tv : 0.2f * tv;
    }

    unsigned long long m2[8];
    {
        const unsigned long long* bmp =
            reinterpret_cast<const unsigned long long*>(sm + SWB + 64 + obase);
        #pragma unroll
        for (int p = 0; p < 8; p++) m2[p] = bmp[p];
    }
    #pragma unroll
    for (int jj = 0; jj < 32; jj++) {
        unsigned long long xj; BCAST(xj, hv[jj]);
        const unsigned long long* wr =
            reinterpret_cast<const unsigned long long*>(sm + SWB + 128 + jj * 32 + obase);
        #pragma unroll
        for (int p = 0; p < 8; p++) FMA2(m2[p], wr[p], xj);
    }
    #pragma unroll
    for (int p = 0; p < 8; p++) {
        float lo, hi; UNPK(lo, hi, m2[p]);
        lo = lo > 0.f ? lo : 0.2f * lo;
        hi = hi > 0.f ? hi : 0.2f * hi;
        sm[H2S + (obase + 2 * p) * 129 + v]     = lo;
        sm[H2S + (obase + 2 * p + 1) * 129 + v] = hi;
    }
    __syncthreads();

    unsigned long long f[8];
    {
        const unsigned long long* bop =
            reinterpret_cast<const unsigned long long*>(sm + SWB + 96 + obase);
        #pragma unroll
        for (int p = 0; p < 8; p++) f[p] = bop[p];
    }
    #pragma unroll
    for (int i = 0; i < 32; i++) {
        float h2 = sm[H2S + i * 129 + v];
        unsigned long long xi; BCAST(xi, h2);
        const unsigned long long* wr =
            reinterpret_cast<const unsigned long long*>(sm + SWB + 1152 + i * 32 + obase);
        #pragma unroll
        for (int p = 0; p < 8; p++) FMA2(f[p], wr[p], xi);
    }

    float* st = g_state + ((size_t)(b * NC) << 15) + v0 + v;
    if (!last) {
        #pragma unroll
        for (int p = 0; p < 8; p++) {
            float t0, t1; UNPK(t0, t1, f[p]);
            int o = obase + 2 * p;
            float s0 = sm[HSO + (32 + o) * 132 + v] + sm[SWB + 32 + o];
            float s1 = sm[HSO + (33 + o) * 132 + v] + sm[SWB + 33 + o];
            st[(size_t)o << 15]       += 0.1f * (t0 + s0);
            st[(size_t)(o + 1) << 15] += 0.1f * (t1 + s1);
        }
    } else {
        float psum = 0.f;
        #pragma unroll
        for (int p = 0; p < 8; p++) {
            float t0, t1; UNPK(t0, t1, f[p]);
            int o = obase + 2 * p;
            float s0 = sm[HSO + (32 + o) * 132 + v] + sm[SWB + 32 + o];
            float s1 = sm[HSO + (33 + o) * 132 + v] + sm[SWB + 33 + o];
            psum += st[(size_t)o << 15]       + 0.1f * (t0 + s0);
            psum += st[(size_t)(o + 1) << 15] + 0.1f * (t1 + s1);
        }
        __syncthreads();
        if (half == 1) sm[H2S + v] = psum;
        __syncthreads();
        if (half == 0)
            out[b * VOL + v0 + v] = (psum + sm[H2S + v]) * (1.f / 32.f);
    }
}

// ---------------- launch ----------------

extern "C" void kernel_launch(void* const* d_in, const int* in_sizes, int n_in,
                              void* d_out, int out_size) {
    const float* z  = (const float*)d_in[0];
    const int*   y  = (const int*)d_in[1];
    const float* hw = (const float*)d_in[2];
    const float* hb = (const float*)d_in[3];
    float* out = (float*)d_out;
    (void)in_sizes; (void)n_in; (void)out_size;

    cudaFuncSetAttribute(k_residual, cudaFuncAttributeMaxDynamicSharedMemorySize,
                         SM_FLOATS * 4);

    k_init<<<dim3(128, 4), 256>>>(z);
    for (int it = 0; it < 4; it++) {
        k_sobel<<<dim3(32, 4), 1024>>>();
        k_fold<<<dim3(4, 4), 256>>>(y, hw, hb);
        k_residual<<<dim3(256, 4), 256, SM_FLOATS * 4>>>(out, it == 3 ? 1 : 0);
    }
}